// round 5
// baseline (speedup 1.0000x reference)
#include <cuda_runtime.h>
#include <cstdint>
#include <cstddef>

// ---------------------------------------------------------------------------
// Problem constants
// ---------------------------------------------------------------------------
#define B_SZ   8192
#define D_IN   19200
#define D1     512
#define D2     256
#define D_PW   128
#define N_PW   25
#define N_DRUG 1448

// ---------------------------------------------------------------------------
// GEMM tiling
// ---------------------------------------------------------------------------
#define BM 128
#define BN 128
#define BK 32
#define STAGES 3
#define ASTR 36    // padded A smem stride (floats): conflict-free frag loads
#define BSTR 136   // padded B smem stride (floats)
#define SMEM_FLOATS (STAGES * (BM * ASTR + BK * BSTR))
#define SMEM_BYTES  (SMEM_FLOATS * 4)

// Scratch (allocation-free rule: __device__ globals)
__device__ float g_h1[B_SZ * D1];   // relu(x@W1+b1)
__device__ float g_h2[B_SZ * D2];   // relu(h1@W2+b2)
__device__ int   g_idx64;           // 1 if drug_indices buffer is int64

// ---------------------------------------------------------------------------
// Small PTX helpers
// ---------------------------------------------------------------------------
__device__ __forceinline__ uint32_t f2tf32(float x) {
    uint32_t r;
    asm("cvt.rna.tf32.f32 %0, %1;" : "=r"(r) : "f"(x));
    return r;
}

__device__ __forceinline__ void cp16(float* s, const float* g) {
    uint32_t sa = (uint32_t)__cvta_generic_to_shared(s);
    asm volatile("cp.async.cg.shared.global [%0], [%1], 16;" :: "r"(sa), "l"(g));
}
__device__ __forceinline__ void cp_commit() {
    asm volatile("cp.async.commit_group;" ::: "memory");
}
__device__ __forceinline__ void cp_wait1() {
    asm volatile("cp.async.wait_group 1;" ::: "memory");
}

__device__ __forceinline__ void mma8(float* c, const uint32_t* a, const uint32_t* b) {
    asm volatile(
        "mma.sync.aligned.m16n8k8.row.col.f32.tf32.tf32.f32 "
        "{%0,%1,%2,%3}, {%4,%5,%6,%7}, {%8,%9}, {%0,%1,%2,%3};"
        : "+f"(c[0]), "+f"(c[1]), "+f"(c[2]), "+f"(c[3])
        : "r"(a[0]), "r"(a[1]), "r"(a[2]), "r"(a[3]),
          "r"(b[0]), "r"(b[1]));
}

// ---------------------------------------------------------------------------
// drug_indices dtype detection.
// If the buffer is int64 (little-endian), every odd 32-bit word is the high
// half of a value in [0,1448) -> always 0. If it is int32, odd words are
// random indices; 4096 of them all zero has probability ~0.
// Deterministic given inputs; flag re-written on every launch (graph-safe).
// ---------------------------------------------------------------------------
__global__ void detect_idx_dtype_kernel(const int* __restrict__ di32) {
    __shared__ int s;
    if (threadIdx.x == 0) s = 0;
    __syncthreads();
    int acc = 0;
    // words [0, 8192) are in-bounds under BOTH interpretations
    for (int i = threadIdx.x; i < B_SZ / 2; i += blockDim.x)
        acc |= di32[2 * i + 1];
    if (acc) atomicOr(&s, 1);
    __syncthreads();
    if (threadIdx.x == 0) g_idx64 = (s == 0) ? 1 : 0;
}

// ---------------------------------------------------------------------------
// Fused GEMM + bias + ReLU:  C[M,N] = relu(A[M,K] @ B[K,N] + bias[N])
// TF32 tensor cores (mma.sync m16n8k8), 3-stage cp.async pipeline.
// Requires M%128==0, N%128==0, K%32==0 (true for both GEMMs here).
// ---------------------------------------------------------------------------
__global__ void __launch_bounds__(256) gemm_bias_relu_kernel(
    const float* __restrict__ A, const float* __restrict__ Bm,
    const float* __restrict__ bias, float* __restrict__ C,
    int M, int N, int K)
{
    extern __shared__ float smem[];
    float* sA = smem;                        // [STAGES][BM][ASTR]
    float* sB = smem + STAGES * BM * ASTR;   // [STAGES][BK][BSTR]

    const int tid  = threadIdx.x;
    const int warp = tid >> 5;
    const int lane = tid & 31;
    const int m0 = blockIdx.x * BM;
    const int n0 = blockIdx.y * BN;
    const int wm = (warp >> 1) * 32;   // warp tile row (4 M-warps)
    const int wn = (warp & 1) * 64;    // warp tile col (2 N-warps)
    const int g  = lane >> 2;          // groupID        (0..7)
    const int tg = lane & 3;           // threadInGroup  (0..3)
    const int KT = K / BK;

    float acc[2][8][4];
    #pragma unroll
    for (int i = 0; i < 2; i++)
        #pragma unroll
        for (int j = 0; j < 8; j++)
            #pragma unroll
            for (int k = 0; k < 4; k++) acc[i][j][k] = 0.f;

    // cp.async lane assignments
    const int ar = tid >> 3;          // 0..31 (A row within pass)
    const int ac = (tid & 7) * 4;     // 0..28 (A col, float4)
    const int br = tid >> 5;          // 0..7  (B row within pass)
    const int bc = (tid & 31) * 4;    // 0..124 (B col, float4)

    auto load_tile = [&](int stage, int kt) {
        const float* Ag = A + (size_t)m0 * K + (size_t)kt * BK;
        float* sAs = sA + stage * BM * ASTR;
        #pragma unroll
        for (int i = 0; i < 4; i++) {
            int r = ar + i * 32;
            cp16(sAs + r * ASTR + ac, Ag + (size_t)r * K + ac);
        }
        const float* Bg = Bm + (size_t)(kt * BK) * N + n0;
        float* sBs = sB + stage * BK * BSTR;
        #pragma unroll
        for (int i = 0; i < 4; i++) {
            int r = br + i * 8;
            cp16(sBs + r * BSTR + bc, Bg + (size_t)r * N + bc);
        }
    };

    auto compute_tile = [&](int stage) {
        const float* sAs = sA + stage * BM * ASTR + wm * ASTR;
        const float* sBs = sB + stage * BK * BSTR + wn;
        #pragma unroll
        for (int kk = 0; kk < 4; kk++) {
            const int k = kk * 8;
            uint32_t aF[2][4];
            uint32_t bF[8][2];
            #pragma unroll
            for (int mt = 0; mt < 2; mt++) {
                const float* ap = sAs + (mt * 16) * ASTR + k;
                aF[mt][0] = f2tf32(ap[g * ASTR + tg]);
                aF[mt][1] = f2tf32(ap[(g + 8) * ASTR + tg]);
                aF[mt][2] = f2tf32(ap[g * ASTR + tg + 4]);
                aF[mt][3] = f2tf32(ap[(g + 8) * ASTR + tg + 4]);
            }
            #pragma unroll
            for (int nt = 0; nt < 8; nt++) {
                const float* bp_ = sBs + (k + tg) * BSTR + nt * 8 + g;
                bF[nt][0] = f2tf32(bp_[0]);
                bF[nt][1] = f2tf32(bp_[4 * BSTR]);
            }
            #pragma unroll
            for (int mt = 0; mt < 2; mt++)
                #pragma unroll
                for (int nt = 0; nt < 8; nt++)
                    mma8(acc[mt][nt], aF[mt], bF[nt]);
        }
    };

    // Prologue: fill STAGES-1 stages
    load_tile(0, 0);
    cp_commit();
    if (KT > 1) load_tile(1, 1);
    cp_commit();

    for (int kt = 0; kt < KT; kt++) {
        cp_wait1();
        __syncthreads();
        int nk = kt + STAGES - 1;
        if (nk < KT) load_tile(nk % STAGES, nk);
        cp_commit();
        compute_tile(kt % STAGES);
        __syncthreads();
    }

    // Epilogue: bias + relu, float2 stores
    #pragma unroll
    for (int mt = 0; mt < 2; mt++) {
        #pragma unroll
        for (int nt = 0; nt < 8; nt++) {
            int row = m0 + wm + mt * 16 + g;
            int col = n0 + wn + nt * 8 + 2 * tg;
            float bv0 = bias[col];
            float bv1 = bias[col + 1];
            float2 v0, v1;
            v0.x = fmaxf(acc[mt][nt][0] + bv0, 0.f);
            v0.y = fmaxf(acc[mt][nt][1] + bv1, 0.f);
            v1.x = fmaxf(acc[mt][nt][2] + bv0, 0.f);
            v1.y = fmaxf(acc[mt][nt][3] + bv1, 0.f);
            *reinterpret_cast<float2*>(C + (size_t)row * N + col)       = v0;
            *reinterpret_cast<float2*>(C + (size_t)(row + 8) * N + col) = v1;
        }
    }
}

// ---------------------------------------------------------------------------
// Fused pathway head + per-drug linear head.
// One 128-thread block per sample. Only the SELECTED pathway is computed
// (reference computes all 25 and selects — 25x redundant).
// out[b] = sum_k relu(h2[b]·Wp[p,k,:] + bp[p,k]) * Wd[d,k] + bd[d]
// ---------------------------------------------------------------------------
__global__ void __launch_bounds__(128) head_kernel(
    const float* __restrict__ h2, const float* __restrict__ Wp,
    const float* __restrict__ bp, const float* __restrict__ Wd,
    const float* __restrict__ bd, const int* __restrict__ di32,
    const int* __restrict__ drug_pw, float* __restrict__ out)
{
    const int b = blockIdx.x;
    const int t = threadIdx.x;  // 0..127 => pathway-head output index k
    __shared__ float hs[D2];
    __shared__ float red[4];

    // Load h2 row (256 floats with 128 threads, float2 each)
    reinterpret_cast<float2*>(hs)[t] =
        reinterpret_cast<const float2*>(h2 + (size_t)b * D2)[t];

    // Index read: int64 buffer -> low word at 2*b; int32 buffer -> word at b.
    int d = g_idx64 ? di32[2 * b] : di32[b];
    d = min(max(d, 0), N_DRUG - 1);          // crash guard
    int p = drug_pw[d];
    p = min(max(p, 0), N_PW - 1);            // crash guard
    __syncthreads();

    const float4* w  = reinterpret_cast<const float4*>(
        Wp + ((size_t)p * D_PW + t) * D2);
    const float4* hv = reinterpret_cast<const float4*>(hs);

    float acc = 0.f;
    #pragma unroll 8
    for (int i = 0; i < D2 / 4; i++) {
        float4 wv = w[i];
        float4 h4 = hv[i];
        acc += wv.x * h4.x + wv.y * h4.y + wv.z * h4.z + wv.w * h4.w;
    }
    acc += bp[p * D_PW + t];
    acc = fmaxf(acc, 0.f) * Wd[(size_t)d * D_PW + t];

    // Block reduction of 128 values
    #pragma unroll
    for (int o = 16; o > 0; o >>= 1)
        acc += __shfl_xor_sync(0xffffffffu, acc, o);
    if ((t & 31) == 0) red[t >> 5] = acc;
    __syncthreads();
    if (t == 0)
        out[b] = red[0] + red[1] + red[2] + red[3] + bd[d];
}

// ---------------------------------------------------------------------------
// Launch
// ---------------------------------------------------------------------------
extern "C" void kernel_launch(void* const* d_in, const int* in_sizes, int n_in,
                              void* d_out, int out_size)
{
    const float* x   = (const float*)d_in[0];
    const float* W1  = (const float*)d_in[1];
    const float* b1  = (const float*)d_in[2];
    const float* W2  = (const float*)d_in[3];
    const float* b2  = (const float*)d_in[4];
    const float* Wp  = (const float*)d_in[5];
    const float* bp  = (const float*)d_in[6];
    const float* Wd  = (const float*)d_in[7];
    const float* bd  = (const float*)d_in[8];
    const int*   di  = (const int*)d_in[9];    // dtype resolved on-device
    const int*   dpw = (const int*)d_in[10];
    float* out = (float*)d_out;

    void *p1 = nullptr, *p2 = nullptr;
    cudaGetSymbolAddress(&p1, g_h1);
    cudaGetSymbolAddress(&p2, g_h2);
    float* h1 = (float*)p1;
    float* h2 = (float*)p2;

    cudaFuncSetAttribute(gemm_bias_relu_kernel,
                         cudaFuncAttributeMaxDynamicSharedMemorySize, SMEM_BYTES);

    dim3 blk(256);
    // Resolve drug_indices dtype (writes g_idx64; graph-replay-safe)
    detect_idx_dtype_kernel<<<1, 256>>>(di);
    // GEMM1: [8192,19200] @ [19200,512] -> h1
    gemm_bias_relu_kernel<<<dim3(B_SZ / BM, D1 / BN), blk, SMEM_BYTES>>>(
        x, W1, b1, h1, B_SZ, D1, D_IN);
    // GEMM2: [8192,512] @ [512,256] -> h2
    gemm_bias_relu_kernel<<<dim3(B_SZ / BM, D2 / BN), blk, SMEM_BYTES>>>(
        h1, W2, b2, h2, B_SZ, D2, D1);
    // Fused pathway + drug head
    head_kernel<<<B_SZ, 128>>>(h2, Wp, bp, Wd, bd, di, dpw, out);
}

// round 6
// speedup vs baseline: 1.2332x; 1.2332x over previous
#include <cuda_runtime.h>
#include <cstdint>
#include <cstddef>

// ---------------------------------------------------------------------------
// Problem constants
// ---------------------------------------------------------------------------
#define B_SZ   8192
#define D_IN   19200
#define D1     512
#define D2     256
#define D_PW   128
#define N_PW   25
#define N_DRUG 1448

// ---------------------------------------------------------------------------
// GEMM tiling: 128x256 CTA tile, 8 warps of 64x64, BK=32, 3-stage cp.async
// ---------------------------------------------------------------------------
#define BM 128
#define BN 256
#define BK 32
#define STAGES 3
#define ASTR 36    // padded A smem stride (floats): conflict-free frag loads
#define BSTR 264   // padded B smem stride (floats): tg*264+g mod 32 distinct
#define SMEM_FLOATS (STAGES * (BM * ASTR + BK * BSTR))
#define SMEM_BYTES  (SMEM_FLOATS * 4)

// Head kernel
#define CHUNK 64
#define WSTR 260   // padded Wp smem row stride (floats); 260*4=1040B, 16B-aligned
#define HEAD_SMEM_BYTES ((128 * WSTR + CHUNK * 256 + 32) * 4 + CHUNK * 8 + 64)

// Scratch (allocation-free rule: __device__ globals)
__device__ float g_h1[B_SZ * D1];       // relu(x@W1+b1)
__device__ float g_h2[B_SZ * D2];       // relu(h1@W2+b2)
__device__ int   g_idx64;               // 1 if drug_indices buffer is int64
__device__ int   g_cnt[N_PW];           // per-pathway sample counts
__device__ int   g_bucket[N_PW][B_SZ];  // per-pathway sample lists

// ---------------------------------------------------------------------------
// Small PTX helpers
// ---------------------------------------------------------------------------
__device__ __forceinline__ uint32_t f2tf32(float x) {
    uint32_t r;
    asm("cvt.rna.tf32.f32 %0, %1;" : "=r"(r) : "f"(x));
    return r;
}

__device__ __forceinline__ void cp16(float* s, const float* g) {
    uint32_t sa = (uint32_t)__cvta_generic_to_shared(s);
    asm volatile("cp.async.cg.shared.global [%0], [%1], 16;" :: "r"(sa), "l"(g));
}
__device__ __forceinline__ void cp_commit() {
    asm volatile("cp.async.commit_group;" ::: "memory");
}
__device__ __forceinline__ void cp_wait1() {
    asm volatile("cp.async.wait_group 1;" ::: "memory");
}

__device__ __forceinline__ void mma8(float* c, const uint32_t* a, const uint32_t* b) {
    asm volatile(
        "mma.sync.aligned.m16n8k8.row.col.f32.tf32.tf32.f32 "
        "{%0,%1,%2,%3}, {%4,%5,%6,%7}, {%8,%9}, {%0,%1,%2,%3};"
        : "+f"(c[0]), "+f"(c[1]), "+f"(c[2]), "+f"(c[3])
        : "r"(a[0]), "r"(a[1]), "r"(a[2]), "r"(a[3]),
          "r"(b[0]), "r"(b[1]));
}

// ---------------------------------------------------------------------------
// drug_indices dtype detection (int64 high words are all zero; int32 is not).
// ---------------------------------------------------------------------------
__global__ void detect_idx_dtype_kernel(const int* __restrict__ di32) {
    __shared__ int s;
    if (threadIdx.x == 0) s = 0;
    __syncthreads();
    int acc = 0;
    for (int i = threadIdx.x; i < B_SZ / 2; i += blockDim.x)
        acc |= di32[2 * i + 1];
    if (acc) atomicOr(&s, 1);
    __syncthreads();
    if (threadIdx.x == 0) g_idx64 = (s == 0) ? 1 : 0;
}

// ---------------------------------------------------------------------------
// Pathway bucketing (re-run every launch: graph-replay safe, deterministic
// output since each sample is computed independently exactly once).
// ---------------------------------------------------------------------------
__global__ void bucket_zero_kernel() {
    if (threadIdx.x < N_PW) g_cnt[threadIdx.x] = 0;
}

__global__ void bucket_fill_kernel(const int* __restrict__ di32,
                                   const int* __restrict__ drug_pw) {
    int b = blockIdx.x * blockDim.x + threadIdx.x;
    if (b >= B_SZ) return;
    int d = g_idx64 ? di32[2 * b] : di32[b];
    d = min(max(d, 0), N_DRUG - 1);
    int p = drug_pw[d];
    p = min(max(p, 0), N_PW - 1);
    int pos = atomicAdd(&g_cnt[p], 1);
    g_bucket[p][pos] = b;
}

// ---------------------------------------------------------------------------
// Fused GEMM + bias + ReLU:  C[M,N] = relu(A[M,K] @ B[K,N] + bias[N])
// TF32 mma.sync m16n8k8, warp tile 64x64, 3-stage cp.async pipeline.
// Requires M%128==0, N%256==0, K%32==0.
// ---------------------------------------------------------------------------
__global__ void __launch_bounds__(256) gemm_bias_relu_kernel(
    const float* __restrict__ A, const float* __restrict__ Bm,
    const float* __restrict__ bias, float* __restrict__ C,
    int M, int N, int K)
{
    extern __shared__ float smem[];
    float* sA = smem;                        // [STAGES][BM][ASTR]
    float* sB = smem + STAGES * BM * ASTR;   // [STAGES][BK][BSTR]

    const int tid  = threadIdx.x;
    const int warp = tid >> 5;
    const int lane = tid & 31;
    const int m0 = blockIdx.x * BM;
    const int n0 = blockIdx.y * BN;
    const int wm = (warp >> 2) * 64;   // 2 M-warps
    const int wn = (warp & 3) * 64;    // 4 N-warps
    const int g  = lane >> 2;          // 0..7
    const int tg = lane & 3;           // 0..3
    const int KT = K / BK;

    float acc[4][8][4];
    #pragma unroll
    for (int i = 0; i < 4; i++)
        #pragma unroll
        for (int j = 0; j < 8; j++)
            #pragma unroll
            for (int k = 0; k < 4; k++) acc[i][j][k] = 0.f;

    // cp.async lane assignments
    const int ar = tid >> 3;          // 0..31 (A row), 4 passes of 32 rows
    const int ac = (tid & 7) * 4;     // A col float4
    const int br = tid >> 6;          // 0..3  (B row), 8 passes of 4 rows
    const int bc = (tid & 63) * 4;    // B col float4 (0..252)

    auto load_tile = [&](int stage, int kt) {
        const float* Ag = A + (size_t)m0 * K + (size_t)kt * BK;
        float* sAs = sA + stage * BM * ASTR;
        #pragma unroll
        for (int i = 0; i < 4; i++) {
            int r = ar + i * 32;
            cp16(sAs + r * ASTR + ac, Ag + (size_t)r * K + ac);
        }
        const float* Bg = Bm + (size_t)(kt * BK) * N + n0;
        float* sBs = sB + stage * BK * BSTR;
        #pragma unroll
        for (int i = 0; i < 8; i++) {
            int r = br + i * 4;
            cp16(sBs + r * BSTR + bc, Bg + (size_t)r * N + bc);
        }
    };

    auto compute_tile = [&](int stage) {
        const float* sAs = sA + stage * BM * ASTR + wm * ASTR;
        const float* sBs = sB + stage * BK * BSTR + wn;
        #pragma unroll
        for (int kk = 0; kk < 4; kk++) {
            const int k = kk * 8;
            uint32_t aF[4][4];
            uint32_t bF[8][2];
            #pragma unroll
            for (int mt = 0; mt < 4; mt++) {
                const float* ap = sAs + (mt * 16) * ASTR + k;
                aF[mt][0] = f2tf32(ap[g * ASTR + tg]);
                aF[mt][1] = f2tf32(ap[(g + 8) * ASTR + tg]);
                aF[mt][2] = f2tf32(ap[g * ASTR + tg + 4]);
                aF[mt][3] = f2tf32(ap[(g + 8) * ASTR + tg + 4]);
            }
            #pragma unroll
            for (int nt = 0; nt < 8; nt++) {
                const float* bp_ = sBs + (k + tg) * BSTR + nt * 8 + g;
                bF[nt][0] = f2tf32(bp_[0]);
                bF[nt][1] = f2tf32(bp_[4 * BSTR]);
            }
            #pragma unroll
            for (int mt = 0; mt < 4; mt++)
                #pragma unroll
                for (int nt = 0; nt < 8; nt++)
                    mma8(acc[mt][nt], aF[mt], bF[nt]);
        }
    };

    // Prologue: fill STAGES-1 stages
    load_tile(0, 0);
    cp_commit();
    if (KT > 1) load_tile(1, 1);
    cp_commit();

    for (int kt = 0; kt < KT; kt++) {
        cp_wait1();
        __syncthreads();
        int nk = kt + STAGES - 1;
        if (nk < KT) load_tile(nk % STAGES, nk);
        cp_commit();
        compute_tile(kt % STAGES);
        __syncthreads();
    }

    // Epilogue: bias + relu, float2 stores
    #pragma unroll
    for (int mt = 0; mt < 4; mt++) {
        #pragma unroll
        for (int nt = 0; nt < 8; nt++) {
            int row = m0 + wm + mt * 16 + g;
            int col = n0 + wn + nt * 8 + 2 * tg;
            float bv0 = bias[col];
            float bv1 = bias[col + 1];
            float2 v0, v1;
            v0.x = fmaxf(acc[mt][nt][0] + bv0, 0.f);
            v0.y = fmaxf(acc[mt][nt][1] + bv1, 0.f);
            v1.x = fmaxf(acc[mt][nt][2] + bv0, 0.f);
            v1.y = fmaxf(acc[mt][nt][3] + bv1, 0.f);
            *reinterpret_cast<float2*>(C + (size_t)row * N + col)       = v0;
            *reinterpret_cast<float2*>(C + (size_t)(row + 8) * N + col) = v1;
        }
    }
}

// ---------------------------------------------------------------------------
// Pathway-grouped head. Block (c, p) handles up to CHUNK samples of pathway p.
// Stages Wp[p] (128x256, padded rows) + CHUNK h2 rows in smem.
// Thread t: output k = t&127, sample-parity group = t>>7; 4 samples per
// inner pass reuse each staged Wp float4 (smem-BW amortization).
// out[b] = sum_k relu(h2[b]. Wp[p,k,:] + bp[p,k]) * Wd[d,k] + bd[d]
// ---------------------------------------------------------------------------
__global__ void __launch_bounds__(256) head_kernel(
    const float* __restrict__ h2, const float* __restrict__ Wp,
    const float* __restrict__ bp, const float* __restrict__ Wd,
    const float* __restrict__ bd, const int* __restrict__ di32,
    float* __restrict__ out)
{
    const int p = blockIdx.y;
    const int c = blockIdx.x;
    const int n = g_cnt[p];
    if (c * CHUNK >= n) return;
    const int nly = min(CHUNK, n - c * CHUNK);

    extern __shared__ float hsm_raw[];
    float* ws  = hsm_raw;                       // [128][WSTR]
    float* hsm = ws + 128 * WSTR;               // [CHUNK][256]
    float* red = hsm + CHUNK * 256;             // [8][4]
    int*   sb  = (int*)(red + 32);              // [CHUNK]
    int*   sd  = sb + CHUNK;                    // [CHUNK]

    const int tid = threadIdx.x;

    // Sample metadata
    if (tid < CHUNK) {
        if (tid < nly) {
            int b = g_bucket[p][c * CHUNK + tid];
            int d = g_idx64 ? di32[2 * b] : di32[b];
            d = min(max(d, 0), N_DRUG - 1);
            sb[tid] = b;
            sd[tid] = d;
        } else {
            sb[tid] = 0;
            sd[tid] = 0;
        }
    }

    // Stage Wp[p] (coalesced global, padded smem rows)
    {
        const float4* Wp4 = reinterpret_cast<const float4*>(
            Wp + (size_t)p * D_PW * 256);
        for (int idx = tid; idx < 128 * 64; idx += 256) {
            int r = idx >> 6, cc = idx & 63;
            float4 v = Wp4[idx];
            *reinterpret_cast<float4*>(ws + r * WSTR + cc * 4) = v;
        }
    }
    __syncthreads();   // sb ready

    // Stage h2 rows (gathered rows, coalesced within each row)
    for (int idx = tid; idx < nly * 64; idx += 256) {
        int s = idx >> 6, cc = idx & 63;
        float4 v = reinterpret_cast<const float4*>(
            h2 + (size_t)sb[s] * 256)[cc];
        *reinterpret_cast<float4*>(hsm + s * 256 + cc * 4) = v;
    }
    __syncthreads();

    const int kk  = tid & 127;
    const int grp = tid >> 7;        // 0/1: even/odd sample slots
    const int wrp = tid >> 5;        // warp id 0..7
    const int lane = tid & 31;
    const float bpv = bp[p * D_PW + kk];
    const float4* wrow = reinterpret_cast<const float4*>(ws + kk * WSTR);

    // 32 sample slots per group, processed 4 at a time
    for (int i0 = 0; i0 < 32; i0 += 4) {
        int s[4];
        const float4* hr[4];
        #pragma unroll
        for (int u = 0; u < 4; u++) {
            s[u] = 2 * (i0 + u) + grp;
            hr[u] = reinterpret_cast<const float4*>(hsm + s[u] * 256);
        }
        float acc0 = 0.f, acc1 = 0.f, acc2 = 0.f, acc3 = 0.f;
        #pragma unroll 8
        for (int j = 0; j < 64; j++) {
            float4 w4 = wrow[j];
            float4 a = hr[0][j], b2 = hr[1][j], c2 = hr[2][j], d2 = hr[3][j];
            acc0 += w4.x * a.x + w4.y * a.y + w4.z * a.z + w4.w * a.w;
            acc1 += w4.x * b2.x + w4.y * b2.y + w4.z * b2.z + w4.w * b2.w;
            acc2 += w4.x * c2.x + w4.y * c2.y + w4.z * c2.z + w4.w * c2.w;
            acc3 += w4.x * d2.x + w4.y * d2.y + w4.z * d2.z + w4.w * d2.w;
        }
        float v[4] = {acc0, acc1, acc2, acc3};
        #pragma unroll
        for (int u = 0; u < 4; u++) {
            float a = fmaxf(v[u] + bpv, 0.f) * Wd[(size_t)sd[s[u]] * D_PW + kk];
            #pragma unroll
            for (int o = 16; o > 0; o >>= 1)
                a += __shfl_xor_sync(0xffffffffu, a, o);
            if (lane == 0) red[wrp * 4 + u] = a;
        }
        __syncthreads();
        if (tid < 8) {
            int gg = tid >> 2, u = tid & 3;
            int ss = 2 * (i0 + u) + gg;
            if (ss < nly) {
                float t = red[(gg * 4 + 0) * 4 + u] + red[(gg * 4 + 1) * 4 + u]
                        + red[(gg * 4 + 2) * 4 + u] + red[(gg * 4 + 3) * 4 + u];
                out[sb[ss]] = t + bd[sd[ss]];
            }
        }
        __syncthreads();
    }
}

// ---------------------------------------------------------------------------
// Launch
// ---------------------------------------------------------------------------
extern "C" void kernel_launch(void* const* d_in, const int* in_sizes, int n_in,
                              void* d_out, int out_size)
{
    const float* x   = (const float*)d_in[0];
    const float* W1  = (const float*)d_in[1];
    const float* b1  = (const float*)d_in[2];
    const float* W2  = (const float*)d_in[3];
    const float* b2  = (const float*)d_in[4];
    const float* Wp  = (const float*)d_in[5];
    const float* bp  = (const float*)d_in[6];
    const float* Wd  = (const float*)d_in[7];
    const float* bd  = (const float*)d_in[8];
    const int*   di  = (const int*)d_in[9];
    const int*   dpw = (const int*)d_in[10];
    float* out = (float*)d_out;

    void *p1 = nullptr, *p2 = nullptr;
    cudaGetSymbolAddress(&p1, g_h1);
    cudaGetSymbolAddress(&p2, g_h2);
    float* h1 = (float*)p1;
    float* h2 = (float*)p2;

    cudaFuncSetAttribute(gemm_bias_relu_kernel,
                         cudaFuncAttributeMaxDynamicSharedMemorySize, SMEM_BYTES);
    cudaFuncSetAttribute(head_kernel,
                         cudaFuncAttributeMaxDynamicSharedMemorySize, HEAD_SMEM_BYTES);

    dim3 blk(256);
    // Resolve drug_indices dtype + pathway buckets (graph-replay-safe)
    detect_idx_dtype_kernel<<<1, 256>>>(di);
    bucket_zero_kernel<<<1, 32>>>();
    bucket_fill_kernel<<<B_SZ / 256, 256>>>(di, dpw);
    // GEMM1: [8192,19200] @ [19200,512] -> h1
    gemm_bias_relu_kernel<<<dim3(B_SZ / BM, D1 / BN), blk, SMEM_BYTES>>>(
        x, W1, b1, h1, B_SZ, D1, D_IN);
    // GEMM2: [8192,512] @ [512,256] -> h2
    gemm_bias_relu_kernel<<<dim3(B_SZ / BM, D2 / BN), blk, SMEM_BYTES>>>(
        h1, W2, b2, h2, B_SZ, D2, D1);
    // Pathway-grouped head
    head_kernel<<<dim3((B_SZ + CHUNK - 1) / CHUNK, N_PW), blk, HEAD_SMEM_BYTES>>>(
        h2, Wp, bp, Wd, bd, di, out);
}